// round 1
// baseline (speedup 1.0000x reference)
#include <cuda_runtime.h>
#include <math.h>

#define NV 50257
#define NE 256
#define NC 48
#define NB 64
#define NT 1024

#define LOG48    3.8712010109078911f
#define T1_LOG48 3960.2386341588226f   /* 1023 * log(48) */

// Scratch (static device globals — no runtime allocation)
__device__ float g_P[NV * NC];     // emb_table @ fc_w^T + fc_b  (9.65 MB)
__device__ float g_bllh[NB];       // per-batch log-likelihood

// ---------------------------------------------------------------------------
// K1: P[v, c] = sum_e emb[v, e] * fcw[c, e] + fcb[c]
// Tile: 64 vocab rows x 48 classes per block, 256 threads.
// Thread (i = tid>>2, q = tid&3) computes row i, classes q*12 .. q*12+11.
// ---------------------------------------------------------------------------
#define MT 64
#define AS 260   // padded A row stride in floats (260 % 32 == 4 -> conflict-free, 16B aligned)

__global__ __launch_bounds__(256, 1)
void k_gemm(const float* __restrict__ emb, const float* __restrict__ fcw,
            const float* __restrict__ fcb) {
    extern __shared__ float sm[];
    float* As = sm;              // [MT][AS]
    float* Ws = sm + MT * AS;    // [NE][NC]  (k-major)
    const int tid = threadIdx.x;
    const int m0 = blockIdx.x * MT;

    // Load W transposed: Ws[k][c] = fcw[c][k]
    for (int idx = tid; idx < NC * NE; idx += 256) {
        int c = idx >> 8, k = idx & 255;
        Ws[k * NC + c] = fcw[idx];
    }
    // Load 64 table rows (coalesced float4)
    const float4* emb4 = (const float4*)emb;
    for (int idx = tid; idx < MT * (NE / 4); idx += 256) {
        int r = idx >> 6, s = idx & 63;
        int row = m0 + r;
        float4 v = make_float4(0.f, 0.f, 0.f, 0.f);
        if (row < NV) v = emb4[row * (NE / 4) + s];
        *(float4*)(As + r * AS + s * 4) = v;
    }
    __syncthreads();

    const int i = tid >> 2;
    const int q = tid & 3;
    const float4* Arow4 = (const float4*)(As + i * AS);
    const float*  Wq    = Ws + q * 12;

    float acc[12];
#pragma unroll
    for (int j = 0; j < 12; j++) acc[j] = 0.f;

#pragma unroll 4
    for (int k4 = 0; k4 < NE / 4; k4++) {
        float4 a = Arow4[k4];
        const float* wk = Wq + (k4 * 4) * NC;
#pragma unroll
        for (int kk = 0; kk < 4; kk++) {
            float av = (kk == 0) ? a.x : (kk == 1) ? a.y : (kk == 2) ? a.z : a.w;
            const float* wr = wk + kk * NC;
#pragma unroll
            for (int j = 0; j < 12; j++) acc[j] += av * wr[j];
        }
    }

    int m = m0 + i;
    if (m < NV) {
        float* o = g_P + m * NC + q * 12;
#pragma unroll
        for (int j = 0; j < 12; j++) o[j] = acc[j] + fcb[q * 12 + j];
    }
}

// ---------------------------------------------------------------------------
// K2: logits[b,t,:] = P[x[b,t],:]   (float4 granularity, 12 per token)
// ---------------------------------------------------------------------------
__global__ __launch_bounds__(256)
void k_gather(const int* __restrict__ x, float4* __restrict__ out) {
    int idx = blockIdx.x * 256 + threadIdx.x;   // grid sized exactly: B*T*12 / 256
    int tok = idx / 12;
    int j = idx - tok * 12;
    int row = x[tok];
    out[idx] = ((const float4*)g_P)[row * 12 + j];
}

// ---------------------------------------------------------------------------
// K3: CRF per batch. Linear-space scaled forward scan.
//   p_0[c] = exp(start[c] + emis_0[c])
//   p_t[c'] = (sum_c p_{t-1}[c] * exp(trans[c,c'])/48) * exp(emis_t[c'])
//   log Z   = log(sum_c p_{T-1}[c]*exp(end[c])) + 1023*log(48)
// One block / batch, 64 threads (2 warps), thread c' owns W[:,c'] in registers.
// ---------------------------------------------------------------------------
__global__ __launch_bounds__(64, 1)
void k_crf(const float* __restrict__ logits, const int* __restrict__ labels,
           const float* __restrict__ st, const float* __restrict__ en,
           const float* __restrict__ tr) {
    __shared__ float pbuf[2][NC];
    const int tid = threadIdx.x;
    const int b = blockIdx.x;
    const float* lg  = logits + (size_t)b * NT * NC;
    const int*   lab = labels + b * NT;

    float wcol[NC];
#pragma unroll
    for (int c = 0; c < NC; c++) wcol[c] = 0.f;
    if (tid < NC) {
#pragma unroll 8
        for (int c = 0; c < NC; c++)
            wcol[c] = __expf(tr[c * NC + tid] - LOG48);
        pbuf[0][tid] = __expf(st[tid] + lg[tid]);
    }

    // depth-2 emission prefetch (covers ~L2 latency)
    float pre0 = 0.f, pre1 = 0.f;
    if (tid < NC) { pre0 = lg[NC + tid]; pre1 = lg[2 * NC + tid]; }
    int cur = 0;
    __syncthreads();

    for (int t = 1; t < NT; t++) {
        float e = __expf(pre0);
        pre0 = pre1;
        int tn = t + 2; if (tn > NT - 1) tn = NT - 1;
        if (tid < NC) pre1 = lg[tn * NC + tid];

        const float4* p4 = (const float4*)pbuf[cur];
        float a0 = 0.f, a1 = 0.f, a2 = 0.f, a3 = 0.f;
#pragma unroll
        for (int j = 0; j < 12; j++) {
            float4 pv = p4[j];
            a0 += pv.x * wcol[4 * j + 0];
            a1 += pv.y * wcol[4 * j + 1];
            a2 += pv.z * wcol[4 * j + 2];
            a3 += pv.w * wcol[4 * j + 3];
        }
        float pn = ((a0 + a1) + (a2 + a3)) * e;
        if (tid < NC) pbuf[cur ^ 1][tid] = pn;
        cur ^= 1;
        __syncthreads();   // single barrier/step (ping-pong buffers)
    }

    float zv = 0.f;
    if (tid < NC) zv = pbuf[cur][tid] * __expf(en[tid]);

    // numerator = start[lab0] + sum_t emis[t,lab_t] + sum_t trans[lab_t,lab_{t+1}] + end[lab_last]
    float np = 0.f;
    for (int t = tid; t < NT; t += 64) {
        int l0 = lab[t];
        np += lg[t * NC + l0];
        if (t < NT - 1) np += tr[l0 * NC + lab[t + 1]];
    }
    if (tid == 0) np += st[lab[0]];
    if (tid == 1) np += en[lab[NT - 1]];

    // deterministic block reduction of zv and np
    float vz = zv, vn = np;
#pragma unroll
    for (int o = 16; o; o >>= 1) {
        vz += __shfl_down_sync(0xffffffffu, vz, o);
        vn += __shfl_down_sync(0xffffffffu, vn, o);
    }
    __shared__ float rz[2], rn[2];
    if ((tid & 31) == 0) { rz[tid >> 5] = vz; rn[tid >> 5] = vn; }
    __syncthreads();
    if (tid == 0) {
        float z   = rz[0] + rz[1];
        float num = rn[0] + rn[1];
        float logz = logf(z) + T1_LOG48;
        g_bllh[b] = num - logz;
    }
}

// ---------------------------------------------------------------------------
// K4: loss = -sum_b llh[b]
// ---------------------------------------------------------------------------
__global__ __launch_bounds__(64)
void k_final(float* __restrict__ out) {
    int tid = threadIdx.x;
    float v = g_bllh[tid];
#pragma unroll
    for (int o = 16; o; o >>= 1) v += __shfl_down_sync(0xffffffffu, v, o);
    __shared__ float r[2];
    if ((tid & 31) == 0) r[tid >> 5] = v;
    __syncthreads();
    if (tid == 0) out[0] = -(r[0] + r[1]);
}

// ---------------------------------------------------------------------------
extern "C" void kernel_launch(void* const* d_in, const int* in_sizes, int n_in,
                              void* d_out, int out_size) {
    const int*   x    = (const int*)d_in[0];
    const int*   lab  = (const int*)d_in[1];
    const float* emb  = (const float*)d_in[2];
    const float* fcw  = (const float*)d_in[3];
    const float* fcb  = (const float*)d_in[4];
    const float* strt = (const float*)d_in[5];
    const float* endt = (const float*)d_in[6];
    const float* trns = (const float*)d_in[7];
    float* out = (float*)d_out;

    size_t smem = (size_t)(MT * AS + NE * NC) * sizeof(float);  // ~113 KB
    cudaFuncSetAttribute(k_gemm, cudaFuncAttributeMaxDynamicSharedMemorySize, (int)smem);

    k_gemm<<<(NV + MT - 1) / MT, 256, smem>>>(emb, fcw, fcb);
    k_gather<<<(NB * NT * (NC / 4)) / 256, 256>>>(x, (float4*)out);
    k_crf<<<NB, 64>>>(out, lab, strt, endt, trns);
    k_final<<<1, 64>>>(out + (out_size - 1));
}

// round 2
// speedup vs baseline: 1.5432x; 1.5432x over previous
#include <cuda_runtime.h>
#include <math.h>

#define NV 50257
#define NE 256
#define NC 48
#define NB 64
#define NT 1024
#define HT 512

#define LOG48    3.8712010109078911f
#define T1_LOG48 3960.2386341588226f   /* 1023 * log(48) */

// Scratch (static device globals — no runtime allocation)
__device__ float g_P[NV * NC];        // emb_table @ fc_w^T + fc_b  (9.65 MB)
__device__ float g_ab[2][NB][NC];     // [0]=alpha_mid (fwd), [1]=beta_mid (bwd)
__device__ float g_num[2 * NB];       // per-(block) partial numerator

// ---------------------------------------------------------------------------
// K1: P[v, c] = sum_e emb[v, e] * fcw[c, e] + fcb[c]
// Tile: 64 vocab rows x 48 classes per block, 256 threads.
// Thread (i = tid>>2, q = tid&3) computes row i, classes q*12 .. q*12+11.
// W read via float4 (3 LDS.128/k instead of 12 LDS.32/k) -> FFMA-issue bound.
// ---------------------------------------------------------------------------
#define MT 64
#define AS 260   // padded A row stride in floats (260 % 32 == 4 -> conflict-free, 16B aligned)

__global__ __launch_bounds__(256, 1)
void k_gemm(const float* __restrict__ emb, const float* __restrict__ fcw,
            const float* __restrict__ fcb) {
    extern __shared__ float sm[];
    float* As = sm;              // [MT][AS]
    float* Ws = sm + MT * AS;    // [NE][NC]  (k-major), 16B-aligned (MT*AS*4 % 16 == 0)
    const int tid = threadIdx.x;
    const int m0 = blockIdx.x * MT;

    // Load W transposed: Ws[k][c] = fcw[c][k]
    for (int idx = tid; idx < NC * NE; idx += 256) {
        int c = idx >> 8, k = idx & 255;
        Ws[k * NC + c] = fcw[idx];
    }
    // Load 64 table rows (coalesced float4)
    const float4* emb4 = (const float4*)emb;
    for (int idx = tid; idx < MT * (NE / 4); idx += 256) {
        int r = idx >> 6, s = idx & 63;
        int row = m0 + r;
        float4 v = make_float4(0.f, 0.f, 0.f, 0.f);
        if (row < NV) v = emb4[row * (NE / 4) + s];
        *(float4*)(As + r * AS + s * 4) = v;
    }
    __syncthreads();

    const int i = tid >> 2;
    const int q = tid & 3;
    const float4* Arow4 = (const float4*)(As + i * AS);
    const float4* W4    = (const float4*)Ws;   // 12 float4 per k-row

    float acc[12];
#pragma unroll
    for (int j = 0; j < 12; j++) acc[j] = 0.f;

#pragma unroll 4
    for (int k4 = 0; k4 < NE / 4; k4++) {
        float4 a = Arow4[k4];
#pragma unroll
        for (int kk = 0; kk < 4; kk++) {
            int k = k4 * 4 + kk;
            float av = (kk == 0) ? a.x : (kk == 1) ? a.y : (kk == 2) ? a.z : a.w;
            float4 w0 = W4[k * 12 + q * 3 + 0];
            float4 w1 = W4[k * 12 + q * 3 + 1];
            float4 w2 = W4[k * 12 + q * 3 + 2];
            acc[0] += av * w0.x;  acc[1] += av * w0.y;
            acc[2] += av * w0.z;  acc[3] += av * w0.w;
            acc[4] += av * w1.x;  acc[5] += av * w1.y;
            acc[6] += av * w1.z;  acc[7] += av * w1.w;
            acc[8] += av * w2.x;  acc[9] += av * w2.y;
            acc[10] += av * w2.z; acc[11] += av * w2.w;
        }
    }

    int m = m0 + i;
    if (m < NV) {
        float* o = g_P + m * NC + q * 12;
#pragma unroll
        for (int j = 0; j < 12; j++) o[j] = acc[j] + fcb[q * 12 + j];
    }
}

// ---------------------------------------------------------------------------
// K2: fused forward/backward CRF scan + logits materialization.
// grid = 128: dir = blockIdx.x & 1 (0 = fwd from t=0, 1 = bwd from t=1023),
// b = blockIdx.x >> 1. Each block does 512 scaled linear-space matvec steps,
// gathering emissions from g_P via x (depth-3 prefetch over L2), and writes
// the raw emission rows to the logits output as a side effect.
//   fwd: a_0 = e_0*exp(st);  a_s = e_s ∘ (W^T a_{s-1})/48,      s=1..511
//   bwd: g_0 = e_1023*exp(en); g_s = e_{1023-s} ∘ (W g_{s-1})/48, s=1..511
//        beta_mid = (W g_511)/48
//   Z*48^-1023 = sum_c a_511[c] * beta_mid[c]
// Also computes this block's half of the path numerator.
// ---------------------------------------------------------------------------
__global__ __launch_bounds__(64, 1)
void k_crf2(const int* __restrict__ x, const int* __restrict__ lab,
            const float* __restrict__ st, const float* __restrict__ en,
            const float* __restrict__ tr, float* __restrict__ logits) {
    __shared__ float pbuf[2][NC];
    __shared__ int xs[HT];
    const int tid = threadIdx.x;
    const int dir = blockIdx.x & 1;
    const int b   = blockIdx.x >> 1;
    const int base = b * NT;
    float* lg = logits + (size_t)base * NC;

    // stage the 512 token ids this block scans (xs[s] = x at tok(s))
    for (int i = tid; i < HT; i += 64) {
        int tok = dir ? (NT - 1 - i) : i;
        xs[i] = x[base + tok];
    }

    float w[NC];
    float boundary = 0.f;
    if (tid < NC) {
        if (dir == 0) {   // owns column tid of W
#pragma unroll 8
            for (int c = 0; c < NC; c++) w[c] = __expf(tr[c * NC + tid] - LOG48);
            boundary = st[tid];
        } else {          // owns row tid of W
#pragma unroll 8
            for (int c = 0; c < NC; c++) w[c] = __expf(tr[tid * NC + c] - LOG48);
            boundary = en[tid];
        }
    }
    __syncthreads();   // xs ready

    // emission prefetch pipeline (raw P values), depth 3
    float rv0 = 0.f, rv1 = 0.f, rv2 = 0.f;
    if (tid < NC) {
        rv0 = g_P[xs[0] * NC + tid];
        rv1 = g_P[xs[1] * NC + tid];
        rv2 = g_P[xs[2] * NC + tid];
    }
    int cur = 0;
    if (tid < NC) {
        pbuf[0][tid] = __expf(rv0 + boundary);           // e_tok0 * exp(boundary)
        int tok0 = dir ? (NT - 1) : 0;
        lg[tok0 * NC + tid] = rv0;                        // materialize logits
    }
    rv0 = rv1; rv1 = rv2;
    if (tid < NC) rv2 = g_P[xs[3] * NC + tid];
    __syncthreads();

    for (int s = 1; s < HT; s++) {
        float eraw = rv0;                 // raw emission for this step
        rv0 = rv1; rv1 = rv2;
        int sp = s + 3; if (sp > HT - 1) sp = HT - 1;
        int rowp = xs[sp];
        float e = __expf(eraw);
        if (tid < NC) rv2 = g_P[rowp * NC + tid];

        const float4* p4 = (const float4*)pbuf[cur];
        float a0 = 0.f, a1 = 0.f, a2 = 0.f, a3 = 0.f;
#pragma unroll
        for (int j = 0; j < 12; j++) {
            float4 pv = p4[j];
            a0 += pv.x * w[4 * j + 0];
            a1 += pv.y * w[4 * j + 1];
            a2 += pv.z * w[4 * j + 2];
            a3 += pv.w * w[4 * j + 3];
        }
        float pn = ((a0 + a1) + (a2 + a3)) * e;
        if (tid < NC) {
            pbuf[cur ^ 1][tid] = pn;
            int tok = dir ? (NT - 1 - s) : s;
            lg[tok * NC + tid] = eraw;
        }
        cur ^= 1;
        __syncthreads();
    }

    // fwd result = alpha_511; bwd needs one more bare matvec (beta_mid)
    float outv = 0.f;
    if (dir == 1) {
        const float4* p4 = (const float4*)pbuf[cur];
        float a0 = 0.f, a1 = 0.f, a2 = 0.f, a3 = 0.f;
#pragma unroll
        for (int j = 0; j < 12; j++) {
            float4 pv = p4[j];
            a0 += pv.x * w[4 * j + 0];
            a1 += pv.y * w[4 * j + 1];
            a2 += pv.z * w[4 * j + 2];
            a3 += pv.w * w[4 * j + 3];
        }
        outv = (a0 + a1) + (a2 + a3);
    } else {
        if (tid < NC) outv = pbuf[cur][tid];
    }
    if (tid < NC) g_ab[dir][b][tid] = outv;

    // ---- numerator half: emissions + transitions in this block's range ----
    float np = 0.f;
    for (int i = tid; i < HT; i += 64) {
        int t = dir ? (HT + i) : i;                 // fwd: 0..511, bwd: 512..1023
        int l = lab[base + t];
        np += g_P[x[base + t] * NC + l];
        int tp = dir ? (511 + i) : i;               // transition pair (tp, tp+1)
        if (dir || tp < 511)
            np += tr[lab[base + tp] * NC + lab[base + tp + 1]];
    }
    if (tid == 0) np += dir ? en[lab[base + NT - 1]] : st[lab[base]];

    // deterministic block reduction
#pragma unroll
    for (int o = 16; o; o >>= 1) np += __shfl_down_sync(0xffffffffu, np, o);
    __shared__ float rn[2];
    if ((tid & 31) == 0) rn[tid >> 5] = np;
    __syncthreads();
    if (tid == 0) g_num[blockIdx.x] = rn[0] + rn[1];
}

// ---------------------------------------------------------------------------
// K3: combine: per-batch llh = num_f + num_b - (log(alpha·beta) + 1023*log48),
// then loss = -sum_b llh.
// ---------------------------------------------------------------------------
__global__ __launch_bounds__(64)
void k_final(float* __restrict__ out) {
    int b = threadIdx.x;
    float dot = 0.f;
#pragma unroll 8
    for (int c = 0; c < NC; c++) dot += g_ab[0][b][c] * g_ab[1][b][c];
    float llh = g_num[2 * b] + g_num[2 * b + 1] - (logf(dot) + T1_LOG48);

    float v = llh;
#pragma unroll
    for (int o = 16; o; o >>= 1) v += __shfl_down_sync(0xffffffffu, v, o);
    __shared__ float r[2];
    if ((threadIdx.x & 31) == 0) r[threadIdx.x >> 5] = v;
    __syncthreads();
    if (threadIdx.x == 0) out[0] = -(r[0] + r[1]);
}

// ---------------------------------------------------------------------------
extern "C" void kernel_launch(void* const* d_in, const int* in_sizes, int n_in,
                              void* d_out, int out_size) {
    const int*   x    = (const int*)d_in[0];
    const int*   lab  = (const int*)d_in[1];
    const float* emb  = (const float*)d_in[2];
    const float* fcw  = (const float*)d_in[3];
    const float* fcb  = (const float*)d_in[4];
    const float* strt = (const float*)d_in[5];
    const float* endt = (const float*)d_in[6];
    const float* trns = (const float*)d_in[7];
    float* out = (float*)d_out;

    size_t smem = (size_t)(MT * AS + NE * NC) * sizeof(float);  // ~113 KB
    cudaFuncSetAttribute(k_gemm, cudaFuncAttributeMaxDynamicSharedMemorySize, (int)smem);

    k_gemm<<<(NV + MT - 1) / MT, 256, smem>>>(emb, fcw, fcb);
    k_crf2<<<2 * NB, 64>>>(x, lab, strt, endt, trns, out);
    k_final<<<1, 64>>>(out + (out_size - 1));
}

// round 5
// speedup vs baseline: 1.9982x; 1.2948x over previous
#include <cuda_runtime.h>
#include <math.h>

#define NV 50257
#define NE 256
#define NC 48
#define NB 64
#define NT 1024
#define HT 512

#define LOG48    3.8712010109078911f
#define T1_LOG48 3960.2386341588226f   /* 1023 * log(48) */

// packed f32x2 helpers (Blackwell: fma.rn.f32x2 / add.rn.f32x2, 64-bit regs)
#define FMA2(acc, a, b) asm("fma.rn.f32x2 %0, %1, %2, %0;" : "+l"(acc) : "l"(a), "l"(b))
#define ADD2(a, b)      asm("add.rn.f32x2 %0, %0, %1;"     : "+l"(a)   : "l"(b))
__device__ __forceinline__ unsigned long long pack2(float lo, float hi) {
    unsigned long long r;
    asm("mov.b64 %0, {%1, %2};" : "=l"(r) : "r"(__float_as_uint(lo)), "r"(__float_as_uint(hi)));
    return r;
}
__device__ __forceinline__ unsigned long long bcast2(float v) {
    unsigned long long r;
    asm("mov.b64 %0, {%1, %1};" : "=l"(r) : "r"(__float_as_uint(v)));
    return r;
}
__device__ __forceinline__ float hadd2(unsigned long long a) {
    unsigned lo, hi;
    asm("mov.b64 {%0, %1}, %2;" : "=r"(lo), "=r"(hi) : "l"(a));
    return __uint_as_float(lo) + __uint_as_float(hi);
}
__device__ __forceinline__ float2 unpk2(unsigned long long a) {
    unsigned lo, hi;
    asm("mov.b64 {%0, %1}, %2;" : "=r"(lo), "=r"(hi) : "l"(a));
    return make_float2(__uint_as_float(lo), __uint_as_float(hi));
}

// Scratch (static device globals — no runtime allocation)
__device__ float g_P[NV * NC];        // emb_table @ fc_w^T + fc_b  (9.65 MB)
__device__ float g_ab[2][NB][NC];     // [0]=alpha_mid (fwd), [1]=beta_mid (bwd)
__device__ float g_num[2 * NB];       // per-block partial numerator
__device__ unsigned g_ctr;            // crf2 completion counter (reset by last block)

// ---------------------------------------------------------------------------
// K1: P[v, c] = sum_e emb[v, e] * fcw[c, e] + fcb[c]
// 256 threads, 128 rows/block. Thread (i = tid>>2, q = tid&3) computes rows
// {m0+i, m0+64+i} x cols [q*12, q*12+12). W staged in smem k-major (48 KB);
// per k-row the 12-col strip = u64 lanes q*6..q*6+5, read as 3x LDS.128
// (offset k*24+q*6 u64 is even -> 16B-aligned). 12 packed FMA2 per k.
// ---------------------------------------------------------------------------
__global__ __launch_bounds__(256)
void k_gemm(const float* __restrict__ emb, const float* __restrict__ fcw,
            const float* __restrict__ fcb) {
    __shared__ __align__(16) float Ws[NE * NC];   // 48 KB, k-major
    const int tid = threadIdx.x;
    const int m0 = blockIdx.x * 128;

    // Stage W transposed: Ws[k*48 + c] = fcw[c*256 + k]
    for (int idx = tid; idx < NC * NE; idx += 256) {
        int c = idx >> 8, k = idx & 255;
        Ws[k * NC + c] = fcw[idx];
    }
    __syncthreads();

    const int i = tid >> 2;
    const int q = tid & 3;
    const int row0 = m0 + i;
    const int row1 = m0 + 64 + i;
    const bool v0 = row0 < NV, v1 = row1 < NV;
    const float4* A0 = (const float4*)emb + (size_t)(v0 ? row0 : NV - 1) * 64;
    const float4* A1 = (const float4*)emb + (size_t)(v1 ? row1 : NV - 1) * 64;
    const unsigned long long* Wq = (const unsigned long long*)Ws + q * 6;

    unsigned long long c0[6], c1[6];
#pragma unroll
    for (int j = 0; j < 6; j++) { c0[j] = 0ull; c1[j] = 0ull; }

#pragma unroll 2
    for (int k4 = 0; k4 < 64; k4++) {
        float4 a0 = A0[k4];
        float4 a1 = A1[k4];
#pragma unroll
        for (int kk = 0; kk < 4; kk++) {
            float av0 = (kk == 0) ? a0.x : (kk == 1) ? a0.y : (kk == 2) ? a0.z : a0.w;
            float av1 = (kk == 0) ? a1.x : (kk == 1) ? a1.y : (kk == 2) ? a1.z : a1.w;
            unsigned long long pa0 = bcast2(av0);
            unsigned long long pa1 = bcast2(av1);
            const unsigned long long* wk = Wq + (size_t)(k4 * 4 + kk) * 24;
            ulonglong2 wA = *(const ulonglong2*)(wk + 0);   // cols 0..3
            ulonglong2 wB = *(const ulonglong2*)(wk + 2);   // cols 4..7
            ulonglong2 wC = *(const ulonglong2*)(wk + 4);   // cols 8..11
            FMA2(c0[0], pa0, wA.x); FMA2(c0[1], pa0, wA.y);
            FMA2(c0[2], pa0, wB.x); FMA2(c0[3], pa0, wB.y);
            FMA2(c0[4], pa0, wC.x); FMA2(c0[5], pa0, wC.y);
            FMA2(c1[0], pa1, wA.x); FMA2(c1[1], pa1, wA.y);
            FMA2(c1[2], pa1, wB.x); FMA2(c1[3], pa1, wB.y);
            FMA2(c1[4], pa1, wC.x); FMA2(c1[5], pa1, wC.y);
        }
    }

    float bias[12];
#pragma unroll
    for (int j = 0; j < 12; j++) bias[j] = fcb[q * 12 + j];

    if (v0) {
        float r[12];
#pragma unroll
        for (int j = 0; j < 6; j++) {
            float2 u = unpk2(c0[j]);
            r[2 * j] = u.x + bias[2 * j];
            r[2 * j + 1] = u.y + bias[2 * j + 1];
        }
        float4* o = (float4*)(g_P + (size_t)row0 * NC + q * 12);
        o[0] = make_float4(r[0], r[1], r[2], r[3]);
        o[1] = make_float4(r[4], r[5], r[6], r[7]);
        o[2] = make_float4(r[8], r[9], r[10], r[11]);
    }
    if (v1) {
        float r[12];
#pragma unroll
        for (int j = 0; j < 6; j++) {
            float2 u = unpk2(c1[j]);
            r[2 * j] = u.x + bias[2 * j];
            r[2 * j + 1] = u.y + bias[2 * j + 1];
        }
        float4* o = (float4*)(g_P + (size_t)row1 * NC + q * 12);
        o[0] = make_float4(r[0], r[1], r[2], r[3]);
        o[1] = make_float4(r[4], r[5], r[6], r[7]);
        o[2] = make_float4(r[8], r[9], r[10], r[11]);
    }
}

// packed 48-dot: sum_c p[c]*w[c]; p = 12 x ulonglong2 (16B-aligned smem),
// w = 24 packed u64 where wp[m] holds classes (2m, 2m+1). 24 FMA2, 6 chains.
__device__ __forceinline__ float dot48(const float* p, const unsigned long long* wp) {
    const ulonglong2* p2 = (const ulonglong2*)p;
    unsigned long long a0 = 0ull, a1 = 0ull, a2 = 0ull,
                       a3 = 0ull, a4 = 0ull, a5 = 0ull;
#pragma unroll
    for (int j = 0; j < 12; j += 3) {
        ulonglong2 v0 = p2[j], v1 = p2[j + 1], v2 = p2[j + 2];
        FMA2(a0, v0.x, wp[2 * j + 0]); FMA2(a1, v0.y, wp[2 * j + 1]);
        FMA2(a2, v1.x, wp[2 * j + 2]); FMA2(a3, v1.y, wp[2 * j + 3]);
        FMA2(a4, v2.x, wp[2 * j + 4]); FMA2(a5, v2.y, wp[2 * j + 5]);
    }
    ADD2(a0, a3); ADD2(a1, a4); ADD2(a2, a5);
    ADD2(a0, a1); ADD2(a0, a2);
    return hadd2(a0);
}

// ---------------------------------------------------------------------------
// K2: fused forward/backward CRF scan + logits materialization + final combine.
// grid = 128: dir = blockIdx.x & 1, b = blockIdx.x >> 1. 512 scaled
// linear-space matvec steps per block; emissions gathered from g_P (depth-3
// prefetch) and written to logits as a side effect. Last block combines.
// ---------------------------------------------------------------------------
__global__ __launch_bounds__(64, 1)
void k_crf2(const int* __restrict__ x, const int* __restrict__ lab,
            const float* __restrict__ st, const float* __restrict__ en,
            const float* __restrict__ tr, float* __restrict__ logits,
            float* __restrict__ loss_out) {
    __shared__ __align__(16) float pbuf[2][NC];
    __shared__ int xs[HT];
    const int tid = threadIdx.x;
    const int dir = blockIdx.x & 1;
    const int b   = blockIdx.x >> 1;
    const int base = b * NT;
    float* lg = logits + (size_t)base * NC;

    for (int s = tid; s < HT; s += 64) {
        int tok = dir ? (NT - 1 - s) : s;
        xs[s] = x[base + tok];
    }

    unsigned long long wp[24];   // wp[m] = classes (2m, 2m+1) of this thread's W line
    float boundary = 0.f;
#pragma unroll
    for (int m = 0; m < 24; m++) wp[m] = 0ull;
    if (tid < NC) {
        if (dir == 0) {   // fwd: owns column tid; sum over rows c
#pragma unroll 4
            for (int m = 0; m < 24; m++)
                wp[m] = pack2(__expf(tr[(2 * m) * NC + tid] - LOG48),
                              __expf(tr[(2 * m + 1) * NC + tid] - LOG48));
            boundary = st[tid];
        } else {          // bwd: owns row tid; sum over cols c
#pragma unroll 4
            for (int m = 0; m < 24; m++)
                wp[m] = pack2(__expf(tr[tid * NC + 2 * m] - LOG48),
                              __expf(tr[tid * NC + 2 * m + 1] - LOG48));
            boundary = en[tid];
        }
    }
    __syncthreads();   // xs ready

    float rv0 = 0.f, rv1 = 0.f, rv2 = 0.f;
    if (tid < NC) {
        rv0 = g_P[xs[0] * NC + tid];
        rv1 = g_P[xs[1] * NC + tid];
        rv2 = g_P[xs[2] * NC + tid];
    }
    int cur = 0;
    if (tid < NC) {
        pbuf[0][tid] = __expf(rv0 + boundary);
        int tok0 = dir ? (NT - 1) : 0;
        lg[tok0 * NC + tid] = rv0;                        // materialize logits
    }
    rv0 = rv1; rv1 = rv2;
    if (tid < NC) rv2 = g_P[xs[3] * NC + tid];
    __syncthreads();

    for (int s = 1; s < HT; s++) {
        float eraw = rv0;
        rv0 = rv1; rv1 = rv2;
        int sp = s + 3; if (sp > HT - 1) sp = HT - 1;
        int rowp = xs[sp];
        float e = __expf(eraw);           // MUFU early (lat 16)
        if (tid < NC) rv2 = g_P[rowp * NC + tid];

        float pn = dot48(pbuf[cur], wp) * e;
        if (tid < NC) {
            pbuf[cur ^ 1][tid] = pn;
            int tok = dir ? (NT - 1 - s) : s;
            lg[tok * NC + tid] = eraw;
        }
        cur ^= 1;
        __syncthreads();
    }

    float outv;
    if (dir == 1) outv = dot48(pbuf[cur], wp);   // beta_mid = (W g_511)/48
    else          outv = (tid < NC) ? pbuf[cur][tid] : 0.f;
    if (tid < NC) g_ab[dir][b][tid] = outv;

    // ---- numerator half ----
    float np = 0.f;
    for (int s = tid; s < HT; s += 64) {
        int t = dir ? (HT + s) : s;
        int l = lab[base + t];
        np += g_P[x[base + t] * NC + l];
        int tp = dir ? (511 + s) : s;
        if (dir || tp < 511)
            np += tr[lab[base + tp] * NC + lab[base + tp + 1]];
    }
    if (tid == 0) np += dir ? en[lab[base + NT - 1]] : st[lab[base]];

#pragma unroll
    for (int o = 16; o; o >>= 1) np += __shfl_down_sync(0xffffffffu, np, o);
    __shared__ float rn[2];
    __shared__ unsigned rank;
    if ((tid & 31) == 0) rn[tid >> 5] = np;
    __syncthreads();
    if (tid == 0) {
        g_num[blockIdx.x] = rn[0] + rn[1];
        __threadfence();
        rank = atomicAdd(&g_ctr, 1u);
    }
    __syncthreads();

    if (rank == 2 * NB - 1) {            // last block combines
        __threadfence();
        int bb = tid;
        float dot = 0.f;
#pragma unroll 8
        for (int c = 0; c < NC; c++) dot += g_ab[0][bb][c] * g_ab[1][bb][c];
        float llh = g_num[2 * bb] + g_num[2 * bb + 1] - (logf(dot) + T1_LOG48);
        float v = llh;
#pragma unroll
        for (int o = 16; o; o >>= 1) v += __shfl_down_sync(0xffffffffu, v, o);
        __shared__ float rr[2];
        if ((tid & 31) == 0) rr[tid >> 5] = v;
        __syncthreads();
        if (tid == 0) {
            loss_out[0] = -(rr[0] + rr[1]);
            g_ctr = 0u;                  // reset for next graph replay
        }
    }
}

// ---------------------------------------------------------------------------
extern "C" void kernel_launch(void* const* d_in, const int* in_sizes, int n_in,
                              void* d_out, int out_size) {
    const int*   x    = (const int*)d_in[0];
    const int*   lab  = (const int*)d_in[1];
    const float* emb  = (const float*)d_in[2];
    const float* fcw  = (const float*)d_in[3];
    const float* fcb  = (const float*)d_in[4];
    const float* strt = (const float*)d_in[5];
    const float* endt = (const float*)d_in[6];
    const float* trns = (const float*)d_in[7];
    float* out = (float*)d_out;

    k_gemm<<<(NV + 127) / 128, 256>>>(emb, fcw, fcb);
    k_crf2<<<2 * NB, 64>>>(x, lab, strt, endt, trns, out, out + (out_size - 1));
}